// round 10
// baseline (speedup 1.0000x reference)
#include <cuda_runtime.h>
#include <cuda_bf16.h>
#include <cstdint>

#define MAXN 50000
#define MAXE 625000
#define FDIM 128
#define NGRAPH 64
#define GN_EPS 1e-5f
#define SCAN_TILE 256

// ---------------- scratch (static device globals; no runtime alloc) ----------
__device__ __align__(16) float g_deg[MAXN];
__device__ __align__(16) float g_p0[(size_t)MAXN * FDIM];  // y@W0 + bias
__device__ __align__(16) float g_p1[(size_t)MAXN * FDIM];  // y@W1
__device__ __align__(16) float g_p2[(size_t)MAXN * FDIM];  // y@W2
__device__ __align__(16) float g_p3[(size_t)MAXN * FDIM];  // y@W3
__device__ __align__(16) float g_u2[(size_t)MAXN * FDIM];  // S*p3 + p2
__device__ __align__(16) float g_u1[(size_t)MAXN * FDIM];  // S*u2 + p1
__device__ __align__(16) float g_out[(size_t)MAXN * FDIM]; // S*u1 + p0
__device__ __align__(16) float g_gsum[NGRAPH * FDIM];
__device__ __align__(16) float g_gsqs[NGRAPH * FDIM];
__device__ float g_gcnt[NGRAPH];
__device__ int   g_rowptr[MAXN + 1];
__device__ int   g_cursor[MAXN];
__device__ int   g_blksum[512];
__device__ __align__(8) int2 g_csr[MAXE];   // {src, bitcast(norm)}
__device__ int   g_src[MAXE];
__device__ int   g_dst[MAXE];
__device__ int   g_batch[MAXN];
__device__ unsigned g_orflag[2];

// ---------------- stream/event pack (program-start init, reused) ------------
struct StreamPack {
    cudaStream_t sB;
    cudaEvent_t evRoot, evG2, evG1, evG0;
    StreamPack() {
        cudaStreamCreateWithFlags(&sB, cudaStreamNonBlocking);
        cudaEventCreateWithFlags(&evRoot, cudaEventDisableTiming);
        cudaEventCreateWithFlags(&evG2, cudaEventDisableTiming);
        cudaEventCreateWithFlags(&evG1, cudaEventDisableTiming);
        cudaEventCreateWithFlags(&evG0, cudaEventDisableTiming);
    }
};
static StreamPack g_sp;

// ---------------- packed f32x2 helpers ----------------
__device__ __forceinline__ unsigned long long pack2(float lo, float hi) {
    unsigned long long r;
    asm("mov.b64 %0, {%1, %2};" : "=l"(r) : "f"(lo), "f"(hi));
    return r;
}
__device__ __forceinline__ void unpack2(unsigned long long v, float& lo, float& hi) {
    asm("mov.b64 {%0, %1}, %2;" : "=f"(lo), "=f"(hi) : "l"(v));
}
__device__ __forceinline__ unsigned long long fma2(unsigned long long a,
                                                   unsigned long long b,
                                                   unsigned long long c) {
    unsigned long long d;
    asm("fma.rn.f32x2 %0, %1, %2, %3;" : "=l"(d) : "l"(a), "l"(b), "l"(c));
    return d;
}

// ---------------- buffer selectors ----------
// read: 0:y 1:p0 2:p1 3:p2 4:p3 5:u2 6:u1
__device__ __forceinline__ const float* buf_read(int i, const float* y) {
    switch (i) {
        case 0: return y;
        case 1: return g_p0;
        case 2: return g_p1;
        case 3: return g_p2;
        case 4: return g_p3;
        case 5: return g_u2;
        default: return g_u1;
    }
}
// write: 1:p0 2:p1 3:p2 4:p3 5:u2 6:u1 7:out
__device__ __forceinline__ float* buf_write(int i) {
    switch (i) {
        case 1: return g_p0;
        case 2: return g_p1;
        case 3: return g_p2;
        case 4: return g_p3;
        case 5: return g_u2;
        case 6: return g_u1;
        default: return g_out;
    }
}

// ---------------- zero small scratch + flags ----------------
__global__ void zero_kernel(int N) {
    int idx = blockIdx.x * blockDim.x + threadIdx.x;
    if (idx < N) { g_deg[idx] = 0.f; g_cursor[idx] = 0; }
    if (idx < NGRAPH * FDIM) { g_gsum[idx] = 0.f; g_gsqs[idx] = 0.f; }
    if (idx < NGRAPH) g_gcnt[idx] = 0.f;
    if (idx < 2) g_orflag[idx] = 0u;
}

// ---------------- dtype detection (sampled): OR odd 32-bit words ------------
__global__ void detect_kernel(const unsigned* __restrict__ ei, int ei_words,
                              const unsigned* __restrict__ bt, int bt_words) {
    __shared__ unsigned s_or[2];
    if (threadIdx.x < 2) s_or[threadIdx.x] = 0u;
    __syncthreads();
    int gidx = blockIdx.x * blockDim.x + threadIdx.x;
    int gstride = gridDim.x * blockDim.x;
    unsigned acc = 0u;
    for (int w = 1 + 2 * gidx; w < ei_words; w += 2 * gstride) acc |= ei[w];
    if (acc) atomicOr(&s_or[0], acc);
    acc = 0u;
    for (int w = 1 + 2 * gidx; w < bt_words; w += 2 * gstride) acc |= bt[w];
    if (acc) atomicOr(&s_or[1], acc);
    __syncthreads();
    if (threadIdx.x == 0 && s_or[0]) atomicOr(&g_orflag[0], s_or[0]);
    if (threadIdx.x == 1 && s_or[1]) atomicOr(&g_orflag[1], s_or[1]);
}

// ---------------- normalize indices to int32 + degree/count -----------------
__global__ void convdeg_kernel(const void* __restrict__ ei,
                               const void* __restrict__ bt,
                               const float* __restrict__ w, int E, int N) {
    int i = blockIdx.x * blockDim.x + threadIdx.x;
    int is64_ei = (g_orflag[0] == 0u);
    int is64_b  = (g_orflag[1] == 0u);
    if (i < E) {
        int s, d;
        if (is64_ei) {
            s = (int)((const long long*)ei)[i];
            d = (int)((const long long*)ei)[(size_t)E + i];
        } else {
            s = ((const int*)ei)[i];
            d = ((const int*)ei)[(size_t)E + i];
        }
        g_src[i] = s;
        g_dst[i] = d;
        if ((unsigned)d < (unsigned)N) {
            atomicAdd(&g_deg[d], w[i]);
            atomicAdd(&g_cursor[d], 1);
        }
    }
    if (i < N) {
        g_batch[i] = is64_b ? (int)((const long long*)bt)[i]
                            : ((const int*)bt)[i];
    }
}

// ---------------- parallel scan ----------------
__global__ void scan1_kernel(int N) {
    __shared__ int sh[SCAN_TILE];
    int t = threadIdx.x;
    int r = blockIdx.x * SCAN_TILE + t;
    sh[t] = (r < N) ? g_cursor[r] : 0;
    __syncthreads();
    for (int off = SCAN_TILE / 2; off > 0; off >>= 1) {
        if (t < off) sh[t] += sh[t + off];
        __syncthreads();
    }
    if (t == 0) g_blksum[blockIdx.x] = sh[0];
}
__global__ void scan2_kernel(int nblk) {
    __shared__ int sh[512];
    int t = threadIdx.x;
    sh[t] = (t < nblk) ? g_blksum[t] : 0;
    __syncthreads();
    for (int off = 1; off < 512; off <<= 1) {
        int v = (t >= off) ? sh[t - off] : 0;
        __syncthreads();
        sh[t] += v;
        __syncthreads();
    }
    g_blksum[t] = (t == 0) ? 0 : sh[t - 1];
}
__global__ void scan3_kernel(int N) {
    __shared__ int sh[SCAN_TILE];
    int t = threadIdx.x;
    int r = blockIdx.x * SCAN_TILE + t;
    int v = (r < N) ? g_cursor[r] : 0;
    sh[t] = v;
    __syncthreads();
    for (int off = 1; off < SCAN_TILE; off <<= 1) {
        int u = (t >= off) ? sh[t - off] : 0;
        __syncthreads();
        sh[t] += u;
        __syncthreads();
    }
    int excl = sh[t] - v + g_blksum[blockIdx.x];
    if (r < N) { g_rowptr[r] = excl; g_cursor[r] = excl; }
    if (r == N - 1) g_rowptr[N] = excl + v;
}

// ---------------- edge norm + scatter into CSR ----------------
__global__ void scatter_kernel(const float* __restrict__ w, int E, int N) {
    int e = blockIdx.x * blockDim.x + threadIdx.x;
    if (e >= E) return;
    int s = g_src[e], d = g_dst[e];
    if ((unsigned)s >= (unsigned)N || (unsigned)d >= (unsigned)N) return;
    float ds = g_deg[s], dd = g_deg[d];
    float is = (ds > 0.f) ? rsqrtf(fmaxf(ds, 1e-30f)) : 0.f;
    float id = (dd > 0.f) ? rsqrtf(fmaxf(dd, 1e-30f)) : 0.f;
    float nrm = is * w[e] * id;
    int pos = atomicAdd(&g_cursor[d], 1);
    if ((unsigned)pos < (unsigned)MAXE)
        g_csr[pos] = make_int2(s, __float_as_int(nrm));
}

// ---------------- gather+add hop: dst = S * u + p  (warp per dst row) --------
__global__ void gather_add_kernel(const float* __restrict__ y,
                                  int usel, int psel, int dsel, int N) {
    int row = (int)(((size_t)blockIdx.x * blockDim.x + threadIdx.x) >> 5);
    int lane = threadIdx.x & 31;
    if (row >= N) return;
    const float4* __restrict__ up = (const float4*)buf_read(usel, y);
    const float4* __restrict__ pp = (const float4*)buf_read(psel, y);
    float4* __restrict__ dn = (float4*)buf_write(dsel);
    int j = g_rowptr[row];
    int jend = g_rowptr[row + 1];
    float4 acc = pp[(size_t)row * 32 + lane];   // + p[row]
    for (; j + 3 < jend; j += 4) {
        int2 e0 = g_csr[j];
        int2 e1 = g_csr[j + 1];
        int2 e2 = g_csr[j + 2];
        int2 e3 = g_csr[j + 3];
        float4 v0 = up[(size_t)e0.x * 32 + lane];
        float4 v1 = up[(size_t)e1.x * 32 + lane];
        float4 v2 = up[(size_t)e2.x * 32 + lane];
        float4 v3 = up[(size_t)e3.x * 32 + lane];
        float w0 = __int_as_float(e0.y), w1 = __int_as_float(e1.y);
        float w2 = __int_as_float(e2.y), w3 = __int_as_float(e3.y);
        acc.x += w0 * v0.x + w1 * v1.x + w2 * v2.x + w3 * v3.x;
        acc.y += w0 * v0.y + w1 * v1.y + w2 * v2.y + w3 * v3.y;
        acc.z += w0 * v0.z + w1 * v1.z + w2 * v2.z + w3 * v3.z;
        acc.w += w0 * v0.w + w1 * v1.w + w2 * v2.w + w3 * v3.w;
    }
    for (; j < jend; ++j) {
        int2 e0 = g_csr[j];
        float w0 = __int_as_float(e0.y);
        float4 v0 = up[(size_t)e0.x * 32 + lane];
        acc.x += w0 * v0.x; acc.y += w0 * v0.y;
        acc.z += w0 * v0.z; acc.w += w0 * v0.w;
    }
    dn[(size_t)row * 32 + lane] = acc;
}

// ---------------- GEMM (f32x2): p = y @ Wk (+ bias for km==0) ----------------
__global__ __launch_bounds__(256) void gemm_y_kernel(
    const float* __restrict__ y, const float* __restrict__ W,
    const float* __restrict__ bias, int N, int km, int dsel, int add_bias)
{
    __shared__ float As[16][128];
    __shared__ float Bs[16][128];
    int tid = threadIdx.x;
    int m0 = blockIdx.x * 128;
    int ty = tid >> 4;     // 0..15
    int tx = tid & 15;     // 0..15
    const float* Wk = W + (size_t)km * FDIM * FDIM;
    float* dst = buf_write(dsel);

    unsigned long long acc2[8][4];
#pragma unroll
    for (int i = 0; i < 8; i++)
#pragma unroll
        for (int j = 0; j < 4; j++) acc2[i][j] = 0ULL;

#pragma unroll 1
    for (int t = 0; t < FDIM / 16; ++t) {
#pragma unroll
        for (int l = 0; l < 2; l++) {
            int idx = tid + l * 256;          // 0..511
            int m  = idx >> 2;                // 0..127
            int kq = (idx & 3) * 4;           // 0,4,8,12
            int row = m0 + m;
            float4 v = make_float4(0.f, 0.f, 0.f, 0.f);
            if (row < N)
                v = *(const float4*)(y + (size_t)row * FDIM + t * 16 + kq);
            int sw = (kq << 1);
            As[kq + 0][m ^ sw] = v.x;
            As[kq + 1][m ^ sw] = v.y;
            As[kq + 2][m ^ sw] = v.z;
            As[kq + 3][m ^ sw] = v.w;
        }
#pragma unroll
        for (int l = 0; l < 2; l++) {
            int idx = tid + l * 256;
            int k  = idx >> 5;
            int fq = (idx & 31) * 4;
            float4 v = *(const float4*)(Wk + (size_t)(t * 16 + k) * FDIM + fq);
            *(float4*)&Bs[k][fq] = v;
        }
        __syncthreads();
#pragma unroll
        for (int k = 0; k < 16; k++) {
            int sw = (k & 12) << 1;
            float a[8];
            *(float4*)&a[0] = *(const float4*)&As[k][(ty * 4) ^ sw];
            *(float4*)&a[4] = *(const float4*)&As[k][(64 + ty * 4) ^ sw];
            const unsigned long long* brow = (const unsigned long long*)&Bs[k][0];
            unsigned long long bp[4];
            bp[0] = brow[tx * 2];
            bp[1] = brow[tx * 2 + 1];
            bp[2] = brow[32 + tx * 2];
            bp[3] = brow[32 + tx * 2 + 1];
#pragma unroll
            for (int i = 0; i < 8; i++) {
                unsigned long long ap = pack2(a[i], a[i]);
                acc2[i][0] = fma2(ap, bp[0], acc2[i][0]);
                acc2[i][1] = fma2(ap, bp[1], acc2[i][1]);
                acc2[i][2] = fma2(ap, bp[2], acc2[i][2]);
                acc2[i][3] = fma2(ap, bp[3], acc2[i][3]);
            }
        }
        __syncthreads();
    }

#pragma unroll
    for (int i = 0; i < 8; i++) {
        int row = m0 + ((i < 4) ? (ty * 4 + i) : (64 + ty * 4 + (i - 4)));
        if (row >= N) continue;
#pragma unroll
        for (int half = 0; half < 2; half++) {
            int f = (half == 0) ? (tx * 4) : (64 + tx * 4);
            float4 v;
            unpack2(acc2[i][half * 2 + 0], v.x, v.y);
            unpack2(acc2[i][half * 2 + 1], v.z, v.w);
            if (add_bias) {
                float4 b = *(const float4*)(bias + f);
                v.x += b.x; v.y += b.y; v.z += b.z; v.w += b.w;
            }
            *(float4*)(dst + (size_t)row * FDIM + f) = v;
        }
    }
}

// ---------------- GraphNorm: one-pass per-graph sum + sumsq ------------------
#define GR 128
__global__ void gstats_kernel(int N) {
    int c = threadIdx.x & 31;
    int h = threadIdx.x >> 5;
    int r0 = blockIdx.x * GR;
    int r1 = min(r0 + GR, N);
    int r = r0 + h;
    if (r >= r1) return;
    int g = g_batch[r];
    float4 s = make_float4(0.f, 0.f, 0.f, 0.f);
    float4 q = make_float4(0.f, 0.f, 0.f, 0.f);
    float cnt = 0.f;
    for (; r < r1; r += 8) {
        int gb = g_batch[r];
        if (gb != g) {
            atomicAdd(&g_gsum[g * FDIM + c * 4 + 0], s.x);
            atomicAdd(&g_gsum[g * FDIM + c * 4 + 1], s.y);
            atomicAdd(&g_gsum[g * FDIM + c * 4 + 2], s.z);
            atomicAdd(&g_gsum[g * FDIM + c * 4 + 3], s.w);
            atomicAdd(&g_gsqs[g * FDIM + c * 4 + 0], q.x);
            atomicAdd(&g_gsqs[g * FDIM + c * 4 + 1], q.y);
            atomicAdd(&g_gsqs[g * FDIM + c * 4 + 2], q.z);
            atomicAdd(&g_gsqs[g * FDIM + c * 4 + 3], q.w);
            if (c == 0) atomicAdd(&g_gcnt[g], cnt);
            s = make_float4(0.f, 0.f, 0.f, 0.f);
            q = make_float4(0.f, 0.f, 0.f, 0.f);
            cnt = 0.f;
            g = gb;
        }
        float4 v = *(const float4*)(g_out + (size_t)r * FDIM + c * 4);
        s.x += v.x; s.y += v.y; s.z += v.z; s.w += v.w;
        q.x += v.x * v.x; q.y += v.y * v.y; q.z += v.z * v.z; q.w += v.w * v.w;
        cnt += 1.f;
    }
    atomicAdd(&g_gsum[g * FDIM + c * 4 + 0], s.x);
    atomicAdd(&g_gsum[g * FDIM + c * 4 + 1], s.y);
    atomicAdd(&g_gsum[g * FDIM + c * 4 + 2], s.z);
    atomicAdd(&g_gsum[g * FDIM + c * 4 + 3], s.w);
    atomicAdd(&g_gsqs[g * FDIM + c * 4 + 0], q.x);
    atomicAdd(&g_gsqs[g * FDIM + c * 4 + 1], q.y);
    atomicAdd(&g_gsqs[g * FDIM + c * 4 + 2], q.z);
    atomicAdd(&g_gsqs[g * FDIM + c * 4 + 3], q.w);
    if (c == 0) atomicAdd(&g_gcnt[g], cnt);
}

// ---------------- final: normalize + relu + residual -------------------------
// var = sumsq/cnt - ms*(2-ms)*mean^2  (xc = x - ms*mean)
__global__ void final_kernel(const float* __restrict__ y,
                             const float* __restrict__ mean_scale,
                             const float* __restrict__ gw,
                             const float* __restrict__ gb,
                             float* __restrict__ res, int N) {
    size_t idx = (size_t)blockIdx.x * blockDim.x + threadIdx.x;
    size_t total = (size_t)N * (FDIM / 4);
    if (idx >= total) return;
    int n = (int)(idx >> 5);
    int c = (int)(idx & 31);
    int f = c * 4;
    int g = g_batch[n] & (NGRAPH - 1);
    float cnt = fmaxf(g_gcnt[g], 1.f);
    float ic = 1.f / cnt;
    float4 o   = *(const float4*)(g_out + (size_t)n * FDIM + f);
    float4 sm  = *(const float4*)(&g_gsum[g * FDIM + f]);
    float4 sq  = *(const float4*)(&g_gsqs[g * FDIM + f]);
    float4 msf = *(const float4*)(mean_scale + f);
    float4 w4  = *(const float4*)(gw + f);
    float4 b4  = *(const float4*)(gb + f);
    float4 y4  = *(const float4*)(y + (size_t)n * FDIM + f);
    float4 r;
    {
        float mean = sm.x * ic;
        float var = sq.x * ic - msf.x * (2.f - msf.x) * mean * mean;
        float xc = o.x - msf.x * mean;
        float hv = w4.x * xc * rsqrtf(var + GN_EPS) + b4.x;
        r.x = y4.x + fmaxf(hv, 0.f);
    }
    {
        float mean = sm.y * ic;
        float var = sq.y * ic - msf.y * (2.f - msf.y) * mean * mean;
        float xc = o.y - msf.y * mean;
        float hv = w4.y * xc * rsqrtf(var + GN_EPS) + b4.y;
        r.y = y4.y + fmaxf(hv, 0.f);
    }
    {
        float mean = sm.z * ic;
        float var = sq.z * ic - msf.z * (2.f - msf.z) * mean * mean;
        float xc = o.z - msf.z * mean;
        float hv = w4.z * xc * rsqrtf(var + GN_EPS) + b4.z;
        r.z = y4.z + fmaxf(hv, 0.f);
    }
    {
        float mean = sm.w * ic;
        float var = sq.w * ic - msf.w * (2.f - msf.w) * mean * mean;
        float xc = o.w - msf.w * mean;
        float hv = w4.w * xc * rsqrtf(var + GN_EPS) + b4.w;
        r.w = y4.w + fmaxf(hv, 0.f);
    }
    *(float4*)(res + (size_t)n * FDIM + f) = r;
}

// ---------------- launch: Horner DAG ----------------------------------------
extern "C" void kernel_launch(void* const* d_in, const int* in_sizes, int n_in,
                              void* d_out, int out_size) {
    const float* y    = (const float*)d_in[0];
    const void*  ei   = d_in[1];
    const float* ew   = (const float*)d_in[2];
    const void*  bt   = d_in[3];
    const float* tagw = (const float*)d_in[4];
    const float* tagb = (const float*)d_in[5];
    const float* gnw  = (const float*)d_in[6];
    const float* gnb  = (const float*)d_in[7];
    const float* gnms = (const float*)d_in[8];
    float* outp = (float*)d_out;

    int N = in_sizes[0] / FDIM;
    int E = in_sizes[2];
    if (N > MAXN) N = MAXN;
    if (E > MAXE) E = MAXE;
    int nscan = (N + SCAN_TILE - 1) / SCAN_TILE;
    int gblocks = (N + 127) / 128;
    cudaStream_t s0 = 0;

    // fork: all 4 GEMMs on stream B — they depend ONLY on inputs (Horner form)
    cudaEventRecord(g_sp.evRoot, s0);
    cudaStreamWaitEvent(g_sp.sB, g_sp.evRoot, 0);
    gemm_y_kernel<<<gblocks, 256, 0, g_sp.sB>>>(y, tagw, tagb, N, 3, 4, 0); // p3
    gemm_y_kernel<<<gblocks, 256, 0, g_sp.sB>>>(y, tagw, tagb, N, 2, 3, 0); // p2
    cudaEventRecord(g_sp.evG2, g_sp.sB);
    gemm_y_kernel<<<gblocks, 256, 0, g_sp.sB>>>(y, tagw, tagb, N, 1, 2, 0); // p1
    cudaEventRecord(g_sp.evG1, g_sp.sB);
    gemm_y_kernel<<<gblocks, 256, 0, g_sp.sB>>>(y, tagw, tagb, N, 0, 1, 1); // p0+bias
    cudaEventRecord(g_sp.evG0, g_sp.sB);

    // main chain: CSR build
    zero_kernel<<<(N + 255) / 256, 256>>>(N);
    {
        int eiw = in_sizes[1]; if (eiw > (1 << 19)) eiw = 1 << 19;
        int btw = in_sizes[3]; if (btw > (1 << 19)) btw = 1 << 19;
        detect_kernel<<<128, 256>>>((const unsigned*)ei, eiw,
                                    (const unsigned*)bt, btw);
    }
    {
        int mx = (E > N) ? E : N;
        convdeg_kernel<<<(mx + 255) / 256, 256>>>(ei, bt, ew, E, N);
    }
    scan1_kernel<<<nscan, SCAN_TILE>>>(N);
    scan2_kernel<<<1, 512>>>(nscan);
    scan3_kernel<<<nscan, SCAN_TILE>>>(N);
    scatter_kernel<<<(E + 255) / 256, 256>>>(ew, E, N);

    // Horner hops: u2 = S p3 + p2;  u1 = S u2 + p1;  out = S u1 + p0
    {
        int warps_per_block = 8;
        int blocks = (N + warps_per_block - 1) / warps_per_block;
        cudaStreamWaitEvent(s0, g_sp.evG2, 0);
        gather_add_kernel<<<blocks, warps_per_block * 32>>>(y, 4, 3, 5, N);
        cudaStreamWaitEvent(s0, g_sp.evG1, 0);
        gather_add_kernel<<<blocks, warps_per_block * 32>>>(y, 5, 2, 6, N);
        cudaStreamWaitEvent(s0, g_sp.evG0, 0);
        gather_add_kernel<<<blocks, warps_per_block * 32>>>(y, 6, 1, 7, N);
    }

    // GraphNorm + epilogue
    gstats_kernel<<<(N + GR - 1) / GR, 256>>>(N);
    {
        size_t total = (size_t)N * (FDIM / 4);
        final_kernel<<<(int)((total + 255) / 256), 256>>>(
            y, gnms, gnw, gnb, outp, N);
    }
}

// round 11
// speedup vs baseline: 1.1654x; 1.1654x over previous
#include <cuda_runtime.h>
#include <cuda_bf16.h>
#include <cstdint>

#define MAXN 50000
#define MAXE 625000
#define FDIM 128
#define NGRAPH 64
#define GN_EPS 1e-5f
#define SCAN_TILE 256

// ---------------- scratch (static device globals; no runtime alloc) ----------
__device__ __align__(16) float g_deg[MAXN];
__device__ __align__(16) float g_p0[(size_t)MAXN * FDIM];  // y@W0 + bias
__device__ __align__(16) float g_p1[(size_t)MAXN * FDIM];  // y@W1
__device__ __align__(16) float g_p2[(size_t)MAXN * FDIM];  // y@W2
__device__ __align__(16) float g_p3[(size_t)MAXN * FDIM];  // y@W3
__device__ __align__(16) float g_u2[(size_t)MAXN * FDIM];  // S*p3 + p2
__device__ __align__(16) float g_u1[(size_t)MAXN * FDIM];  // S*u2 + p1
__device__ __align__(16) float g_out[(size_t)MAXN * FDIM]; // S*u1 + p0
__device__ __align__(16) float g_gsum[NGRAPH * FDIM];
__device__ __align__(16) float g_gsqs[NGRAPH * FDIM];
__device__ float g_gcnt[NGRAPH];
__device__ int   g_rowptr[MAXN + 1];
__device__ int   g_cursor[MAXN];
__device__ int   g_blksum[512];
__device__ __align__(8) int2 g_csr[MAXE];   // {src, bitcast(norm)}
__device__ int   g_src[MAXE];
__device__ int   g_dst[MAXE];
__device__ int   g_batch[MAXN];
__device__ unsigned g_orflag[2];

// ---------------- stream/event pack (program-start init, reused) ------------
struct StreamPack {
    cudaStream_t sB;
    cudaEvent_t evRoot, evG2, evG1, evG0;
    StreamPack() {
        cudaStreamCreateWithFlags(&sB, cudaStreamNonBlocking);
        cudaEventCreateWithFlags(&evRoot, cudaEventDisableTiming);
        cudaEventCreateWithFlags(&evG2, cudaEventDisableTiming);
        cudaEventCreateWithFlags(&evG1, cudaEventDisableTiming);
        cudaEventCreateWithFlags(&evG0, cudaEventDisableTiming);
    }
};
static StreamPack g_sp;

// ---------------- packed f32x2 helpers ----------------
__device__ __forceinline__ unsigned long long pack2(float lo, float hi) {
    unsigned long long r;
    asm("mov.b64 %0, {%1, %2};" : "=l"(r) : "f"(lo), "f"(hi));
    return r;
}
__device__ __forceinline__ void unpack2(unsigned long long v, float& lo, float& hi) {
    asm("mov.b64 {%0, %1}, %2;" : "=f"(lo), "=f"(hi) : "l"(v));
}
__device__ __forceinline__ unsigned long long fma2(unsigned long long a,
                                                   unsigned long long b,
                                                   unsigned long long c) {
    unsigned long long d;
    asm("fma.rn.f32x2 %0, %1, %2, %3;" : "=l"(d) : "l"(a), "l"(b), "l"(c));
    return d;
}

// ---------------- buffer selectors ----------
// read: 0:y 1:p0 2:p1 3:p2 4:p3 5:u2 6:u1
__device__ __forceinline__ const float* buf_read(int i, const float* y) {
    switch (i) {
        case 0: return y;
        case 1: return g_p0;
        case 2: return g_p1;
        case 3: return g_p2;
        case 4: return g_p3;
        case 5: return g_u2;
        default: return g_u1;
    }
}
// write: 1:p0 2:p1 3:p2 4:p3 5:u2 6:u1 7:out
__device__ __forceinline__ float* buf_write(int i) {
    switch (i) {
        case 1: return g_p0;
        case 2: return g_p1;
        case 3: return g_p2;
        case 4: return g_p3;
        case 5: return g_u2;
        case 6: return g_u1;
        default: return g_out;
    }
}

// ---------------- zero small scratch + flags ----------------
__global__ void zero_kernel(int N) {
    int idx = blockIdx.x * blockDim.x + threadIdx.x;
    if (idx < N) { g_deg[idx] = 0.f; g_cursor[idx] = 0; }
    if (idx < NGRAPH * FDIM) { g_gsum[idx] = 0.f; g_gsqs[idx] = 0.f; }
    if (idx < NGRAPH) g_gcnt[idx] = 0.f;
    if (idx < 2) g_orflag[idx] = 0u;
}

// ---------------- dtype detection (sampled): OR odd 32-bit words ------------
__global__ void detect_kernel(const unsigned* __restrict__ ei, int ei_words,
                              const unsigned* __restrict__ bt, int bt_words) {
    __shared__ unsigned s_or[2];
    if (threadIdx.x < 2) s_or[threadIdx.x] = 0u;
    __syncthreads();
    int gidx = blockIdx.x * blockDim.x + threadIdx.x;
    int gstride = gridDim.x * blockDim.x;
    unsigned acc = 0u;
    for (int w = 1 + 2 * gidx; w < ei_words; w += 2 * gstride) acc |= ei[w];
    if (acc) atomicOr(&s_or[0], acc);
    acc = 0u;
    for (int w = 1 + 2 * gidx; w < bt_words; w += 2 * gstride) acc |= bt[w];
    if (acc) atomicOr(&s_or[1], acc);
    __syncthreads();
    if (threadIdx.x == 0 && s_or[0]) atomicOr(&g_orflag[0], s_or[0]);
    if (threadIdx.x == 1 && s_or[1]) atomicOr(&g_orflag[1], s_or[1]);
}

// ---------------- normalize indices to int32 + degree/count -----------------
__global__ void convdeg_kernel(const void* __restrict__ ei,
                               const void* __restrict__ bt,
                               const float* __restrict__ w, int E, int N) {
    int i = blockIdx.x * blockDim.x + threadIdx.x;
    int is64_ei = (g_orflag[0] == 0u);
    int is64_b  = (g_orflag[1] == 0u);
    if (i < E) {
        int s, d;
        if (is64_ei) {
            s = (int)((const long long*)ei)[i];
            d = (int)((const long long*)ei)[(size_t)E + i];
        } else {
            s = ((const int*)ei)[i];
            d = ((const int*)ei)[(size_t)E + i];
        }
        g_src[i] = s;
        g_dst[i] = d;
        if ((unsigned)d < (unsigned)N) {
            atomicAdd(&g_deg[d], w[i]);
            atomicAdd(&g_cursor[d], 1);
        }
    }
    if (i < N) {
        g_batch[i] = is64_b ? (int)((const long long*)bt)[i]
                            : ((const int*)bt)[i];
    }
}

// ---------------- parallel scan ----------------
__global__ void scan1_kernel(int N) {
    __shared__ int sh[SCAN_TILE];
    int t = threadIdx.x;
    int r = blockIdx.x * SCAN_TILE + t;
    sh[t] = (r < N) ? g_cursor[r] : 0;
    __syncthreads();
    for (int off = SCAN_TILE / 2; off > 0; off >>= 1) {
        if (t < off) sh[t] += sh[t + off];
        __syncthreads();
    }
    if (t == 0) g_blksum[blockIdx.x] = sh[0];
}
__global__ void scan2_kernel(int nblk) {
    __shared__ int sh[512];
    int t = threadIdx.x;
    sh[t] = (t < nblk) ? g_blksum[t] : 0;
    __syncthreads();
    for (int off = 1; off < 512; off <<= 1) {
        int v = (t >= off) ? sh[t - off] : 0;
        __syncthreads();
        sh[t] += v;
        __syncthreads();
    }
    g_blksum[t] = (t == 0) ? 0 : sh[t - 1];
}
__global__ void scan3_kernel(int N) {
    __shared__ int sh[SCAN_TILE];
    int t = threadIdx.x;
    int r = blockIdx.x * SCAN_TILE + t;
    int v = (r < N) ? g_cursor[r] : 0;
    sh[t] = v;
    __syncthreads();
    for (int off = 1; off < SCAN_TILE; off <<= 1) {
        int u = (t >= off) ? sh[t - off] : 0;
        __syncthreads();
        sh[t] += u;
        __syncthreads();
    }
    int excl = sh[t] - v + g_blksum[blockIdx.x];
    if (r < N) { g_rowptr[r] = excl; g_cursor[r] = excl; }
    if (r == N - 1) g_rowptr[N] = excl + v;
}

// ---------------- edge norm + scatter into CSR ----------------
__global__ void scatter_kernel(const float* __restrict__ w, int E, int N) {
    int e = blockIdx.x * blockDim.x + threadIdx.x;
    if (e >= E) return;
    int s = g_src[e], d = g_dst[e];
    if ((unsigned)s >= (unsigned)N || (unsigned)d >= (unsigned)N) return;
    float ds = g_deg[s], dd = g_deg[d];
    float is = (ds > 0.f) ? rsqrtf(fmaxf(ds, 1e-30f)) : 0.f;
    float id = (dd > 0.f) ? rsqrtf(fmaxf(dd, 1e-30f)) : 0.f;
    float nrm = is * w[e] * id;
    int pos = atomicAdd(&g_cursor[d], 1);
    if ((unsigned)pos < (unsigned)MAXE)
        g_csr[pos] = make_int2(s, __float_as_int(nrm));
}

// ---------------- gather+add hop: dst = S * u + p  (warp per dst row) --------
__global__ void gather_add_kernel(const float* __restrict__ y,
                                  int usel, int psel, int dsel, int N) {
    int row = (int)(((size_t)blockIdx.x * blockDim.x + threadIdx.x) >> 5);
    int lane = threadIdx.x & 31;
    if (row >= N) return;
    const float4* __restrict__ up = (const float4*)buf_read(usel, y);
    const float4* __restrict__ pp = (const float4*)buf_read(psel, y);
    float4* __restrict__ dn = (float4*)buf_write(dsel);
    int j = g_rowptr[row];
    int jend = g_rowptr[row + 1];
    float4 acc = pp[(size_t)row * 32 + lane];   // + p[row]
    for (; j + 3 < jend; j += 4) {
        int2 e0 = g_csr[j];
        int2 e1 = g_csr[j + 1];
        int2 e2 = g_csr[j + 2];
        int2 e3 = g_csr[j + 3];
        float4 v0 = up[(size_t)e0.x * 32 + lane];
        float4 v1 = up[(size_t)e1.x * 32 + lane];
        float4 v2 = up[(size_t)e2.x * 32 + lane];
        float4 v3 = up[(size_t)e3.x * 32 + lane];
        float w0 = __int_as_float(e0.y), w1 = __int_as_float(e1.y);
        float w2 = __int_as_float(e2.y), w3 = __int_as_float(e3.y);
        acc.x += w0 * v0.x + w1 * v1.x + w2 * v2.x + w3 * v3.x;
        acc.y += w0 * v0.y + w1 * v1.y + w2 * v2.y + w3 * v3.y;
        acc.z += w0 * v0.z + w1 * v1.z + w2 * v2.z + w3 * v3.z;
        acc.w += w0 * v0.w + w1 * v1.w + w2 * v2.w + w3 * v3.w;
    }
    for (; j < jend; ++j) {
        int2 e0 = g_csr[j];
        float w0 = __int_as_float(e0.y);
        float4 v0 = up[(size_t)e0.x * 32 + lane];
        acc.x += w0 * v0.x; acc.y += w0 * v0.y;
        acc.z += w0 * v0.z; acc.w += w0 * v0.w;
    }
    dn[(size_t)row * 32 + lane] = acc;
}

// ---------------- GEMM (f32x2): p = y @ Wk (+ bias for km==0) ----------------
// BM=64, BN=128, BK=16, 128 threads, 8x8 micro-tile. 3 blocks/SM.
__global__ __launch_bounds__(128, 3) void gemm_y_kernel(
    const float* __restrict__ y, const float* __restrict__ W,
    const float* __restrict__ bias, int N, int km, int dsel, int add_bias)
{
    __shared__ float As[16][64];
    __shared__ float Bs[16][128];
    int tid = threadIdx.x;
    int m0 = blockIdx.x * 64;
    int ty = tid >> 4;     // 0..7  (M groups)
    int tx = tid & 15;     // 0..15 (N groups)
    const float* Wk = W + (size_t)km * FDIM * FDIM;
    float* dst = buf_write(dsel);

    unsigned long long acc2[8][4];
#pragma unroll
    for (int i = 0; i < 8; i++)
#pragma unroll
        for (int j = 0; j < 4; j++) acc2[i][j] = 0ULL;

#pragma unroll 1
    for (int t = 0; t < FDIM / 16; ++t) {
        // load A tile 64x16: 256 float4, 2 per thread (transposed, swizzled)
#pragma unroll
        for (int l = 0; l < 2; l++) {
            int idx = tid + l * 128;          // 0..255
            int m  = idx >> 2;                // 0..63
            int kq = (idx & 3) * 4;           // 0,4,8,12
            int row = m0 + m;
            float4 v = make_float4(0.f, 0.f, 0.f, 0.f);
            if (row < N)
                v = *(const float4*)(y + (size_t)row * FDIM + t * 16 + kq);
            int sw = (kq << 1);
            As[kq + 0][m ^ sw] = v.x;
            As[kq + 1][m ^ sw] = v.y;
            As[kq + 2][m ^ sw] = v.z;
            As[kq + 3][m ^ sw] = v.w;
        }
        // load B tile 16x128: 512 float4, 4 per thread
#pragma unroll
        for (int l = 0; l < 4; l++) {
            int idx = tid + l * 128;          // 0..511
            int k  = idx >> 5;                // 0..15
            int fq = (idx & 31) * 4;
            float4 v = *(const float4*)(Wk + (size_t)(t * 16 + k) * FDIM + fq);
            *(float4*)&Bs[k][fq] = v;
        }
        __syncthreads();
#pragma unroll
        for (int k = 0; k < 16; k++) {
            int sw = (k & 12) << 1;
            float a[8];
            *(float4*)&a[0] = *(const float4*)&As[k][(ty * 4) ^ sw];
            *(float4*)&a[4] = *(const float4*)&As[k][(32 + ty * 4) ^ sw];
            const unsigned long long* brow = (const unsigned long long*)&Bs[k][0];
            unsigned long long bp[4];
            bp[0] = brow[tx * 2];
            bp[1] = brow[tx * 2 + 1];
            bp[2] = brow[32 + tx * 2];
            bp[3] = brow[32 + tx * 2 + 1];
#pragma unroll
            for (int i = 0; i < 8; i++) {
                unsigned long long ap = pack2(a[i], a[i]);
                acc2[i][0] = fma2(ap, bp[0], acc2[i][0]);
                acc2[i][1] = fma2(ap, bp[1], acc2[i][1]);
                acc2[i][2] = fma2(ap, bp[2], acc2[i][2]);
                acc2[i][3] = fma2(ap, bp[3], acc2[i][3]);
            }
        }
        __syncthreads();
    }

#pragma unroll
    for (int i = 0; i < 8; i++) {
        int row = m0 + ((i < 4) ? (ty * 4 + i) : (32 + ty * 4 + (i - 4)));
        if (row >= N) continue;
#pragma unroll
        for (int half = 0; half < 2; half++) {
            int f = (half == 0) ? (tx * 4) : (64 + tx * 4);
            float4 v;
            unpack2(acc2[i][half * 2 + 0], v.x, v.y);
            unpack2(acc2[i][half * 2 + 1], v.z, v.w);
            if (add_bias) {
                float4 b = *(const float4*)(bias + f);
                v.x += b.x; v.y += b.y; v.z += b.z; v.w += b.w;
            }
            *(float4*)(dst + (size_t)row * FDIM + f) = v;
        }
    }
}

// ---------------- GraphNorm: one-pass per-graph sum + sumsq ------------------
#define GR 128
__global__ void gstats_kernel(int N) {
    int c = threadIdx.x & 31;
    int h = threadIdx.x >> 5;
    int r0 = blockIdx.x * GR;
    int r1 = min(r0 + GR, N);
    int r = r0 + h;
    if (r >= r1) return;
    int g = g_batch[r];
    float4 s = make_float4(0.f, 0.f, 0.f, 0.f);
    float4 q = make_float4(0.f, 0.f, 0.f, 0.f);
    float cnt = 0.f;
    for (; r < r1; r += 8) {
        int gb = g_batch[r];
        if (gb != g) {
            atomicAdd(&g_gsum[g * FDIM + c * 4 + 0], s.x);
            atomicAdd(&g_gsum[g * FDIM + c * 4 + 1], s.y);
            atomicAdd(&g_gsum[g * FDIM + c * 4 + 2], s.z);
            atomicAdd(&g_gsum[g * FDIM + c * 4 + 3], s.w);
            atomicAdd(&g_gsqs[g * FDIM + c * 4 + 0], q.x);
            atomicAdd(&g_gsqs[g * FDIM + c * 4 + 1], q.y);
            atomicAdd(&g_gsqs[g * FDIM + c * 4 + 2], q.z);
            atomicAdd(&g_gsqs[g * FDIM + c * 4 + 3], q.w);
            if (c == 0) atomicAdd(&g_gcnt[g], cnt);
            s = make_float4(0.f, 0.f, 0.f, 0.f);
            q = make_float4(0.f, 0.f, 0.f, 0.f);
            cnt = 0.f;
            g = gb;
        }
        float4 v = *(const float4*)(g_out + (size_t)r * FDIM + c * 4);
        s.x += v.x; s.y += v.y; s.z += v.z; s.w += v.w;
        q.x += v.x * v.x; q.y += v.y * v.y; q.z += v.z * v.z; q.w += v.w * v.w;
        cnt += 1.f;
    }
    atomicAdd(&g_gsum[g * FDIM + c * 4 + 0], s.x);
    atomicAdd(&g_gsum[g * FDIM + c * 4 + 1], s.y);
    atomicAdd(&g_gsum[g * FDIM + c * 4 + 2], s.z);
    atomicAdd(&g_gsum[g * FDIM + c * 4 + 3], s.w);
    atomicAdd(&g_gsqs[g * FDIM + c * 4 + 0], q.x);
    atomicAdd(&g_gsqs[g * FDIM + c * 4 + 1], q.y);
    atomicAdd(&g_gsqs[g * FDIM + c * 4 + 2], q.z);
    atomicAdd(&g_gsqs[g * FDIM + c * 4 + 3], q.w);
    if (c == 0) atomicAdd(&g_gcnt[g], cnt);
}

// ---------------- final: normalize + relu + residual -------------------------
// var = sumsq/cnt - ms*(2-ms)*mean^2  (xc = x - ms*mean)
__global__ void final_kernel(const float* __restrict__ y,
                             const float* __restrict__ mean_scale,
                             const float* __restrict__ gw,
                             const float* __restrict__ gb,
                             float* __restrict__ res, int N) {
    size_t idx = (size_t)blockIdx.x * blockDim.x + threadIdx.x;
    size_t total = (size_t)N * (FDIM / 4);
    if (idx >= total) return;
    int n = (int)(idx >> 5);
    int c = (int)(idx & 31);
    int f = c * 4;
    int g = g_batch[n] & (NGRAPH - 1);
    float cnt = fmaxf(g_gcnt[g], 1.f);
    float ic = 1.f / cnt;
    float4 o   = *(const float4*)(g_out + (size_t)n * FDIM + f);
    float4 sm  = *(const float4*)(&g_gsum[g * FDIM + f]);
    float4 sq  = *(const float4*)(&g_gsqs[g * FDIM + f]);
    float4 msf = *(const float4*)(mean_scale + f);
    float4 w4  = *(const float4*)(gw + f);
    float4 b4  = *(const float4*)(gb + f);
    float4 y4  = *(const float4*)(y + (size_t)n * FDIM + f);
    float4 r;
    {
        float mean = sm.x * ic;
        float var = sq.x * ic - msf.x * (2.f - msf.x) * mean * mean;
        float xc = o.x - msf.x * mean;
        float hv = w4.x * xc * rsqrtf(var + GN_EPS) + b4.x;
        r.x = y4.x + fmaxf(hv, 0.f);
    }
    {
        float mean = sm.y * ic;
        float var = sq.y * ic - msf.y * (2.f - msf.y) * mean * mean;
        float xc = o.y - msf.y * mean;
        float hv = w4.y * xc * rsqrtf(var + GN_EPS) + b4.y;
        r.y = y4.y + fmaxf(hv, 0.f);
    }
    {
        float mean = sm.z * ic;
        float var = sq.z * ic - msf.z * (2.f - msf.z) * mean * mean;
        float xc = o.z - msf.z * mean;
        float hv = w4.z * xc * rsqrtf(var + GN_EPS) + b4.z;
        r.z = y4.z + fmaxf(hv, 0.f);
    }
    {
        float mean = sm.w * ic;
        float var = sq.w * ic - msf.w * (2.f - msf.w) * mean * mean;
        float xc = o.w - msf.w * mean;
        float hv = w4.w * xc * rsqrtf(var + GN_EPS) + b4.w;
        r.w = y4.w + fmaxf(hv, 0.f);
    }
    *(float4*)(res + (size_t)n * FDIM + f) = r;
}

// ---------------- launch: Horner DAG ----------------------------------------
extern "C" void kernel_launch(void* const* d_in, const int* in_sizes, int n_in,
                              void* d_out, int out_size) {
    const float* y    = (const float*)d_in[0];
    const void*  ei   = d_in[1];
    const float* ew   = (const float*)d_in[2];
    const void*  bt   = d_in[3];
    const float* tagw = (const float*)d_in[4];
    const float* tagb = (const float*)d_in[5];
    const float* gnw  = (const float*)d_in[6];
    const float* gnb  = (const float*)d_in[7];
    const float* gnms = (const float*)d_in[8];
    float* outp = (float*)d_out;

    int N = in_sizes[0] / FDIM;
    int E = in_sizes[2];
    if (N > MAXN) N = MAXN;
    if (E > MAXE) E = MAXE;
    int nscan = (N + SCAN_TILE - 1) / SCAN_TILE;
    int gblocks = (N + 63) / 64;
    cudaStream_t s0 = 0;

    // fork: all 4 GEMMs on stream B — they depend ONLY on inputs (Horner form)
    cudaEventRecord(g_sp.evRoot, s0);
    cudaStreamWaitEvent(g_sp.sB, g_sp.evRoot, 0);
    gemm_y_kernel<<<gblocks, 128, 0, g_sp.sB>>>(y, tagw, tagb, N, 3, 4, 0); // p3
    gemm_y_kernel<<<gblocks, 128, 0, g_sp.sB>>>(y, tagw, tagb, N, 2, 3, 0); // p2
    cudaEventRecord(g_sp.evG2, g_sp.sB);
    gemm_y_kernel<<<gblocks, 128, 0, g_sp.sB>>>(y, tagw, tagb, N, 1, 2, 0); // p1
    cudaEventRecord(g_sp.evG1, g_sp.sB);
    gemm_y_kernel<<<gblocks, 128, 0, g_sp.sB>>>(y, tagw, tagb, N, 0, 1, 1); // p0+bias
    cudaEventRecord(g_sp.evG0, g_sp.sB);

    // main chain: CSR build
    zero_kernel<<<(N + 255) / 256, 256>>>(N);
    {
        int eiw = in_sizes[1]; if (eiw > (1 << 19)) eiw = 1 << 19;
        int btw = in_sizes[3]; if (btw > (1 << 19)) btw = 1 << 19;
        detect_kernel<<<128, 256>>>((const unsigned*)ei, eiw,
                                    (const unsigned*)bt, btw);
    }
    {
        int mx = (E > N) ? E : N;
        convdeg_kernel<<<(mx + 255) / 256, 256>>>(ei, bt, ew, E, N);
    }
    scan1_kernel<<<nscan, SCAN_TILE>>>(N);
    scan2_kernel<<<1, 512>>>(nscan);
    scan3_kernel<<<nscan, SCAN_TILE>>>(N);
    scatter_kernel<<<(E + 255) / 256, 256>>>(ew, E, N);

    // Horner hops: u2 = S p3 + p2;  u1 = S u2 + p1;  out = S u1 + p0
    {
        int warps_per_block = 8;
        int blocks = (N + warps_per_block - 1) / warps_per_block;
        cudaStreamWaitEvent(s0, g_sp.evG2, 0);
        gather_add_kernel<<<blocks, warps_per_block * 32>>>(y, 4, 3, 5, N);
        cudaStreamWaitEvent(s0, g_sp.evG1, 0);
        gather_add_kernel<<<blocks, warps_per_block * 32>>>(y, 5, 2, 6, N);
        cudaStreamWaitEvent(s0, g_sp.evG0, 0);
        gather_add_kernel<<<blocks, warps_per_block * 32>>>(y, 6, 1, 7, N);
    }

    // GraphNorm + epilogue
    gstats_kernel<<<(N + GR - 1) / GR, 256>>>(N);
    {
        size_t total = (size_t)N * (FDIM / 4);
        final_kernel<<<(int)((total + 255) / 256), 256>>>(
            y, gnms, gnw, gnb, outp, N);
    }
}

// round 12
// speedup vs baseline: 1.1739x; 1.0073x over previous
#include <cuda_runtime.h>
#include <cuda_bf16.h>
#include <cstdint>

#define MAXN 50000
#define MAXE 625000
#define FDIM 128
#define NGRAPH 64
#define GN_EPS 1e-5f
#define SCAN_TILE 256

// ---------------- scratch (static device globals; no runtime alloc) ----------
__device__ __align__(16) float g_deg[MAXN];
__device__ __align__(16) float g_p0[(size_t)MAXN * FDIM];  // y@W0 + bias
__device__ __align__(16) float g_p1[(size_t)MAXN * FDIM];  // y@W1
__device__ __align__(16) float g_p2[(size_t)MAXN * FDIM];  // y@W2
__device__ __align__(16) float g_p3[(size_t)MAXN * FDIM];  // y@W3
__device__ __align__(16) float g_u2[(size_t)MAXN * FDIM];  // S*p3 + p2
__device__ __align__(16) float g_u1[(size_t)MAXN * FDIM];  // S*u2 + p1
__device__ __align__(16) float g_out[(size_t)MAXN * FDIM]; // S*u1 + p0
__device__ __align__(16) float g_gsum[NGRAPH * FDIM];
__device__ __align__(16) float g_gsqs[NGRAPH * FDIM];
__device__ float g_gcnt[NGRAPH];
__device__ int   g_rowptr[MAXN + 1];
__device__ int   g_cursor[MAXN];
__device__ int   g_blksum[512];
__device__ __align__(8) int2 g_csr[MAXE];   // {src, bitcast(norm)}
__device__ int   g_src[MAXE];
__device__ int   g_dst[MAXE];
__device__ int   g_batch[MAXN];
__device__ unsigned g_orflag[2];

// ---------------- stream/event pack (program-start init, reused) ------------
struct StreamPack {
    cudaStream_t sB;
    cudaEvent_t evRoot, evG2, evG1, evG0;
    StreamPack() {
        int lo = 0, hi = 0;
        cudaDeviceGetStreamPriorityRange(&lo, &hi);   // hi = highest priority
        cudaStreamCreateWithPriority(&sB, cudaStreamNonBlocking, hi);
        cudaEventCreateWithFlags(&evRoot, cudaEventDisableTiming);
        cudaEventCreateWithFlags(&evG2, cudaEventDisableTiming);
        cudaEventCreateWithFlags(&evG1, cudaEventDisableTiming);
        cudaEventCreateWithFlags(&evG0, cudaEventDisableTiming);
    }
};
static StreamPack g_sp;

// ---------------- packed f32x2 helpers ----------------
__device__ __forceinline__ unsigned long long pack2(float lo, float hi) {
    unsigned long long r;
    asm("mov.b64 %0, {%1, %2};" : "=l"(r) : "f"(lo), "f"(hi));
    return r;
}
__device__ __forceinline__ void unpack2(unsigned long long v, float& lo, float& hi) {
    asm("mov.b64 {%0, %1}, %2;" : "=f"(lo), "=f"(hi) : "l"(v));
}
__device__ __forceinline__ unsigned long long fma2(unsigned long long a,
                                                   unsigned long long b,
                                                   unsigned long long c) {
    unsigned long long d;
    asm("fma.rn.f32x2 %0, %1, %2, %3;" : "=l"(d) : "l"(a), "l"(b), "l"(c));
    return d;
}

// ---------------- buffer selectors ----------
// read: 0:y 1:p0 2:p1 3:p2 4:p3 5:u2 6:u1
__device__ __forceinline__ const float* buf_read(int i, const float* y) {
    switch (i) {
        case 0: return y;
        case 1: return g_p0;
        case 2: return g_p1;
        case 3: return g_p2;
        case 4: return g_p3;
        case 5: return g_u2;
        default: return g_u1;
    }
}
// write: 1:p0 2:p1 3:p2 4:p3 5:u2 6:u1 7:out
__device__ __forceinline__ float* buf_write(int i) {
    switch (i) {
        case 1: return g_p0;
        case 2: return g_p1;
        case 3: return g_p2;
        case 4: return g_p3;
        case 5: return g_u2;
        case 6: return g_u1;
        default: return g_out;
    }
}

// ---------------- zero small scratch + flags ----------------
__global__ void zero_kernel(int N) {
    int idx = blockIdx.x * blockDim.x + threadIdx.x;
    if (idx < N) { g_deg[idx] = 0.f; g_cursor[idx] = 0; }
    if (idx < NGRAPH * FDIM) { g_gsum[idx] = 0.f; g_gsqs[idx] = 0.f; }
    if (idx < NGRAPH) g_gcnt[idx] = 0.f;
    if (idx < 2) g_orflag[idx] = 0u;
}

// ---------------- dtype detection (sampled): OR odd 32-bit words ------------
__global__ void detect_kernel(const unsigned* __restrict__ ei, int ei_words,
                              const unsigned* __restrict__ bt, int bt_words) {
    __shared__ unsigned s_or[2];
    if (threadIdx.x < 2) s_or[threadIdx.x] = 0u;
    __syncthreads();
    int gidx = blockIdx.x * blockDim.x + threadIdx.x;
    int gstride = gridDim.x * blockDim.x;
    unsigned acc = 0u;
    for (int w = 1 + 2 * gidx; w < ei_words; w += 2 * gstride) acc |= ei[w];
    if (acc) atomicOr(&s_or[0], acc);
    acc = 0u;
    for (int w = 1 + 2 * gidx; w < bt_words; w += 2 * gstride) acc |= bt[w];
    if (acc) atomicOr(&s_or[1], acc);
    __syncthreads();
    if (threadIdx.x == 0 && s_or[0]) atomicOr(&g_orflag[0], s_or[0]);
    if (threadIdx.x == 1 && s_or[1]) atomicOr(&g_orflag[1], s_or[1]);
}

// ---------------- normalize indices to int32 + degree/count -----------------
__global__ void convdeg_kernel(const void* __restrict__ ei,
                               const void* __restrict__ bt,
                               const float* __restrict__ w, int E, int N) {
    int i = blockIdx.x * blockDim.x + threadIdx.x;
    int is64_ei = (g_orflag[0] == 0u);
    int is64_b  = (g_orflag[1] == 0u);
    if (i < E) {
        int s, d;
        if (is64_ei) {
            s = (int)((const long long*)ei)[i];
            d = (int)((const long long*)ei)[(size_t)E + i];
        } else {
            s = ((const int*)ei)[i];
            d = ((const int*)ei)[(size_t)E + i];
        }
        g_src[i] = s;
        g_dst[i] = d;
        if ((unsigned)d < (unsigned)N) {
            atomicAdd(&g_deg[d], w[i]);
            atomicAdd(&g_cursor[d], 1);
        }
    }
    if (i < N) {
        g_batch[i] = is64_b ? (int)((const long long*)bt)[i]
                            : ((const int*)bt)[i];
    }
}

// ---------------- parallel scan ----------------
__global__ void scan1_kernel(int N) {
    __shared__ int sh[SCAN_TILE];
    int t = threadIdx.x;
    int r = blockIdx.x * SCAN_TILE + t;
    sh[t] = (r < N) ? g_cursor[r] : 0;
    __syncthreads();
    for (int off = SCAN_TILE / 2; off > 0; off >>= 1) {
        if (t < off) sh[t] += sh[t + off];
        __syncthreads();
    }
    if (t == 0) g_blksum[blockIdx.x] = sh[0];
}
__global__ void scan2_kernel(int nblk) {
    __shared__ int sh[512];
    int t = threadIdx.x;
    sh[t] = (t < nblk) ? g_blksum[t] : 0;
    __syncthreads();
    for (int off = 1; off < 512; off <<= 1) {
        int v = (t >= off) ? sh[t - off] : 0;
        __syncthreads();
        sh[t] += v;
        __syncthreads();
    }
    g_blksum[t] = (t == 0) ? 0 : sh[t - 1];
}
__global__ void scan3_kernel(int N) {
    __shared__ int sh[SCAN_TILE];
    int t = threadIdx.x;
    int r = blockIdx.x * SCAN_TILE + t;
    int v = (r < N) ? g_cursor[r] : 0;
    sh[t] = v;
    __syncthreads();
    for (int off = 1; off < SCAN_TILE; off <<= 1) {
        int u = (t >= off) ? sh[t - off] : 0;
        __syncthreads();
        sh[t] += u;
        __syncthreads();
    }
    int excl = sh[t] - v + g_blksum[blockIdx.x];
    if (r < N) { g_rowptr[r] = excl; g_cursor[r] = excl; }
    if (r == N - 1) g_rowptr[N] = excl + v;
}

// ---------------- edge norm + scatter into CSR ----------------
__global__ void scatter_kernel(const float* __restrict__ w, int E, int N) {
    int e = blockIdx.x * blockDim.x + threadIdx.x;
    if (e >= E) return;
    int s = g_src[e], d = g_dst[e];
    if ((unsigned)s >= (unsigned)N || (unsigned)d >= (unsigned)N) return;
    float ds = g_deg[s], dd = g_deg[d];
    float is = (ds > 0.f) ? rsqrtf(fmaxf(ds, 1e-30f)) : 0.f;
    float id = (dd > 0.f) ? rsqrtf(fmaxf(dd, 1e-30f)) : 0.f;
    float nrm = is * w[e] * id;
    int pos = atomicAdd(&g_cursor[d], 1);
    if ((unsigned)pos < (unsigned)MAXE)
        g_csr[pos] = make_int2(s, __float_as_int(nrm));
}

// ---------------- gather+add hop: dst = S * u + p  (warp per dst row) --------
__global__ void gather_add_kernel(const float* __restrict__ y,
                                  int usel, int psel, int dsel, int N) {
    int row = (int)(((size_t)blockIdx.x * blockDim.x + threadIdx.x) >> 5);
    int lane = threadIdx.x & 31;
    if (row >= N) return;
    const float4* __restrict__ up = (const float4*)buf_read(usel, y);
    const float4* __restrict__ pp = (const float4*)buf_read(psel, y);
    float4* __restrict__ dn = (float4*)buf_write(dsel);
    int j = g_rowptr[row];
    int jend = g_rowptr[row + 1];
    float4 acc = pp[(size_t)row * 32 + lane];   // + p[row]
    for (; j + 3 < jend; j += 4) {
        int2 e0 = g_csr[j];
        int2 e1 = g_csr[j + 1];
        int2 e2 = g_csr[j + 2];
        int2 e3 = g_csr[j + 3];
        float4 v0 = up[(size_t)e0.x * 32 + lane];
        float4 v1 = up[(size_t)e1.x * 32 + lane];
        float4 v2 = up[(size_t)e2.x * 32 + lane];
        float4 v3 = up[(size_t)e3.x * 32 + lane];
        float w0 = __int_as_float(e0.y), w1 = __int_as_float(e1.y);
        float w2 = __int_as_float(e2.y), w3 = __int_as_float(e3.y);
        acc.x += w0 * v0.x + w1 * v1.x + w2 * v2.x + w3 * v3.x;
        acc.y += w0 * v0.y + w1 * v1.y + w2 * v2.y + w3 * v3.y;
        acc.z += w0 * v0.z + w1 * v1.z + w2 * v2.z + w3 * v3.z;
        acc.w += w0 * v0.w + w1 * v1.w + w2 * v2.w + w3 * v3.w;
    }
    for (; j < jend; ++j) {
        int2 e0 = g_csr[j];
        float w0 = __int_as_float(e0.y);
        float4 v0 = up[(size_t)e0.x * 32 + lane];
        acc.x += w0 * v0.x; acc.y += w0 * v0.y;
        acc.z += w0 * v0.z; acc.w += w0 * v0.w;
    }
    dn[(size_t)row * 32 + lane] = acc;
}

// ---------------- GEMM (f32x2): p = y @ Wk (+ bias for km==0) ----------------
// BM=64, BN=128, BK=16, 128 threads, 8x8 micro-tile, 4 blocks/SM forced.
__global__ __launch_bounds__(128, 4) void gemm_y_kernel(
    const float* __restrict__ y, const float* __restrict__ W,
    const float* __restrict__ bias, int N, int km, int dsel, int add_bias)
{
    __shared__ float As[16][64];
    __shared__ float Bs[16][128];
    int tid = threadIdx.x;
    int m0 = blockIdx.x * 64;
    int ty = tid >> 4;     // 0..7  (M groups)
    int tx = tid & 15;     // 0..15 (N groups)
    const float* Wk = W + (size_t)km * FDIM * FDIM;
    float* dst = buf_write(dsel);

    unsigned long long acc2[8][4];
#pragma unroll
    for (int i = 0; i < 8; i++)
#pragma unroll
        for (int j = 0; j < 4; j++) acc2[i][j] = 0ULL;

#pragma unroll 1
    for (int t = 0; t < FDIM / 16; ++t) {
        // load A tile 64x16: 256 float4, 2 per thread (transposed, swizzled)
#pragma unroll
        for (int l = 0; l < 2; l++) {
            int idx = tid + l * 128;          // 0..255
            int m  = idx >> 2;                // 0..63
            int kq = (idx & 3) * 4;           // 0,4,8,12
            int row = m0 + m;
            float4 v = make_float4(0.f, 0.f, 0.f, 0.f);
            if (row < N)
                v = *(const float4*)(y + (size_t)row * FDIM + t * 16 + kq);
            int sw = (kq << 1);
            As[kq + 0][m ^ sw] = v.x;
            As[kq + 1][m ^ sw] = v.y;
            As[kq + 2][m ^ sw] = v.z;
            As[kq + 3][m ^ sw] = v.w;
        }
        // load B tile 16x128: 512 float4, 4 per thread
#pragma unroll
        for (int l = 0; l < 4; l++) {
            int idx = tid + l * 128;          // 0..511
            int k  = idx >> 5;                // 0..15
            int fq = (idx & 31) * 4;
            float4 v = *(const float4*)(Wk + (size_t)(t * 16 + k) * FDIM + fq);
            *(float4*)&Bs[k][fq] = v;
        }
        __syncthreads();
#pragma unroll
        for (int k = 0; k < 16; k++) {
            int sw = (k & 12) << 1;
            float a[8];
            *(float4*)&a[0] = *(const float4*)&As[k][(ty * 4) ^ sw];
            *(float4*)&a[4] = *(const float4*)&As[k][(32 + ty * 4) ^ sw];
            const unsigned long long* brow = (const unsigned long long*)&Bs[k][0];
            unsigned long long bp[4];
            bp[0] = brow[tx * 2];
            bp[1] = brow[tx * 2 + 1];
            bp[2] = brow[32 + tx * 2];
            bp[3] = brow[32 + tx * 2 + 1];
#pragma unroll
            for (int i = 0; i < 8; i++) {
                unsigned long long ap = pack2(a[i], a[i]);
                acc2[i][0] = fma2(ap, bp[0], acc2[i][0]);
                acc2[i][1] = fma2(ap, bp[1], acc2[i][1]);
                acc2[i][2] = fma2(ap, bp[2], acc2[i][2]);
                acc2[i][3] = fma2(ap, bp[3], acc2[i][3]);
            }
        }
        __syncthreads();
    }

#pragma unroll
    for (int i = 0; i < 8; i++) {
        int row = m0 + ((i < 4) ? (ty * 4 + i) : (32 + ty * 4 + (i - 4)));
        if (row >= N) continue;
#pragma unroll
        for (int half = 0; half < 2; half++) {
            int f = (half == 0) ? (tx * 4) : (64 + tx * 4);
            float4 v;
            unpack2(acc2[i][half * 2 + 0], v.x, v.y);
            unpack2(acc2[i][half * 2 + 1], v.z, v.w);
            if (add_bias) {
                float4 b = *(const float4*)(bias + f);
                v.x += b.x; v.y += b.y; v.z += b.z; v.w += b.w;
            }
            *(float4*)(dst + (size_t)row * FDIM + f) = v;
        }
    }
}

// ---------------- GraphNorm: one-pass per-graph sum + sumsq ------------------
#define GR 128
__global__ void gstats_kernel(int N) {
    int c = threadIdx.x & 31;
    int h = threadIdx.x >> 5;
    int r0 = blockIdx.x * GR;
    int r1 = min(r0 + GR, N);
    int r = r0 + h;
    if (r >= r1) return;
    int g = g_batch[r];
    float4 s = make_float4(0.f, 0.f, 0.f, 0.f);
    float4 q = make_float4(0.f, 0.f, 0.f, 0.f);
    float cnt = 0.f;
    for (; r < r1; r += 8) {
        int gb = g_batch[r];
        if (gb != g) {
            atomicAdd(&g_gsum[g * FDIM + c * 4 + 0], s.x);
            atomicAdd(&g_gsum[g * FDIM + c * 4 + 1], s.y);
            atomicAdd(&g_gsum[g * FDIM + c * 4 + 2], s.z);
            atomicAdd(&g_gsum[g * FDIM + c * 4 + 3], s.w);
            atomicAdd(&g_gsqs[g * FDIM + c * 4 + 0], q.x);
            atomicAdd(&g_gsqs[g * FDIM + c * 4 + 1], q.y);
            atomicAdd(&g_gsqs[g * FDIM + c * 4 + 2], q.z);
            atomicAdd(&g_gsqs[g * FDIM + c * 4 + 3], q.w);
            if (c == 0) atomicAdd(&g_gcnt[g], cnt);
            s = make_float4(0.f, 0.f, 0.f, 0.f);
            q = make_float4(0.f, 0.f, 0.f, 0.f);
            cnt = 0.f;
            g = gb;
        }
        float4 v = *(const float4*)(g_out + (size_t)r * FDIM + c * 4);
        s.x += v.x; s.y += v.y; s.z += v.z; s.w += v.w;
        q.x += v.x * v.x; q.y += v.y * v.y; q.z += v.z * v.z; q.w += v.w * v.w;
        cnt += 1.f;
    }
    atomicAdd(&g_gsum[g * FDIM + c * 4 + 0], s.x);
    atomicAdd(&g_gsum[g * FDIM + c * 4 + 1], s.y);
    atomicAdd(&g_gsum[g * FDIM + c * 4 + 2], s.z);
    atomicAdd(&g_gsum[g * FDIM + c * 4 + 3], s.w);
    atomicAdd(&g_gsqs[g * FDIM + c * 4 + 0], q.x);
    atomicAdd(&g_gsqs[g * FDIM + c * 4 + 1], q.y);
    atomicAdd(&g_gsqs[g * FDIM + c * 4 + 2], q.z);
    atomicAdd(&g_gsqs[g * FDIM + c * 4 + 3], q.w);
    if (c == 0) atomicAdd(&g_gcnt[g], cnt);
}

// ---------------- final: normalize + relu + residual -------------------------
// var = sumsq/cnt - ms*(2-ms)*mean^2  (xc = x - ms*mean)
__global__ void final_kernel(const float* __restrict__ y,
                             const float* __restrict__ mean_scale,
                             const float* __restrict__ gw,
                             const float* __restrict__ gb,
                             float* __restrict__ res, int N) {
    size_t idx = (size_t)blockIdx.x * blockDim.x + threadIdx.x;
    size_t total = (size_t)N * (FDIM / 4);
    if (idx >= total) return;
    int n = (int)(idx >> 5);
    int c = (int)(idx & 31);
    int f = c * 4;
    int g = g_batch[n] & (NGRAPH - 1);
    float cnt = fmaxf(g_gcnt[g], 1.f);
    float ic = 1.f / cnt;
    float4 o   = *(const float4*)(g_out + (size_t)n * FDIM + f);
    float4 sm  = *(const float4*)(&g_gsum[g * FDIM + f]);
    float4 sq  = *(const float4*)(&g_gsqs[g * FDIM + f]);
    float4 msf = *(const float4*)(mean_scale + f);
    float4 w4  = *(const float4*)(gw + f);
    float4 b4  = *(const float4*)(gb + f);
    float4 y4  = *(const float4*)(y + (size_t)n * FDIM + f);
    float4 r;
    {
        float mean = sm.x * ic;
        float var = sq.x * ic - msf.x * (2.f - msf.x) * mean * mean;
        float xc = o.x - msf.x * mean;
        float hv = w4.x * xc * rsqrtf(var + GN_EPS) + b4.x;
        r.x = y4.x + fmaxf(hv, 0.f);
    }
    {
        float mean = sm.y * ic;
        float var = sq.y * ic - msf.y * (2.f - msf.y) * mean * mean;
        float xc = o.y - msf.y * mean;
        float hv = w4.y * xc * rsqrtf(var + GN_EPS) + b4.y;
        r.y = y4.y + fmaxf(hv, 0.f);
    }
    {
        float mean = sm.z * ic;
        float var = sq.z * ic - msf.z * (2.f - msf.z) * mean * mean;
        float xc = o.z - msf.z * mean;
        float hv = w4.z * xc * rsqrtf(var + GN_EPS) + b4.z;
        r.z = y4.z + fmaxf(hv, 0.f);
    }
    {
        float mean = sm.w * ic;
        float var = sq.w * ic - msf.w * (2.f - msf.w) * mean * mean;
        float xc = o.w - msf.w * mean;
        float hv = w4.w * xc * rsqrtf(var + GN_EPS) + b4.w;
        r.w = y4.w + fmaxf(hv, 0.f);
    }
    *(float4*)(res + (size_t)n * FDIM + f) = r;
}

// ---------------- launch: Horner DAG ----------------------------------------
extern "C" void kernel_launch(void* const* d_in, const int* in_sizes, int n_in,
                              void* d_out, int out_size) {
    const float* y    = (const float*)d_in[0];
    const void*  ei   = d_in[1];
    const float* ew   = (const float*)d_in[2];
    const void*  bt   = d_in[3];
    const float* tagw = (const float*)d_in[4];
    const float* tagb = (const float*)d_in[5];
    const float* gnw  = (const float*)d_in[6];
    const float* gnb  = (const float*)d_in[7];
    const float* gnms = (const float*)d_in[8];
    float* outp = (float*)d_out;

    int N = in_sizes[0] / FDIM;
    int E = in_sizes[2];
    if (N > MAXN) N = MAXN;
    if (E > MAXE) E = MAXE;
    int nscan = (N + SCAN_TILE - 1) / SCAN_TILE;
    int gblocks = (N + 63) / 64;
    cudaStream_t s0 = 0;

    // fork: all 4 GEMMs on high-priority stream B (Horner: depend only on y)
    cudaEventRecord(g_sp.evRoot, s0);
    cudaStreamWaitEvent(g_sp.sB, g_sp.evRoot, 0);
    gemm_y_kernel<<<gblocks, 128, 0, g_sp.sB>>>(y, tagw, tagb, N, 3, 4, 0); // p3
    gemm_y_kernel<<<gblocks, 128, 0, g_sp.sB>>>(y, tagw, tagb, N, 2, 3, 0); // p2
    cudaEventRecord(g_sp.evG2, g_sp.sB);
    gemm_y_kernel<<<gblocks, 128, 0, g_sp.sB>>>(y, tagw, tagb, N, 1, 2, 0); // p1
    cudaEventRecord(g_sp.evG1, g_sp.sB);
    gemm_y_kernel<<<gblocks, 128, 0, g_sp.sB>>>(y, tagw, tagb, N, 0, 1, 1); // p0+bias
    cudaEventRecord(g_sp.evG0, g_sp.sB);

    // main chain: CSR build
    zero_kernel<<<(N + 255) / 256, 256>>>(N);
    {
        int eiw = in_sizes[1]; if (eiw > (1 << 19)) eiw = 1 << 19;
        int btw = in_sizes[3]; if (btw > (1 << 19)) btw = 1 << 19;
        detect_kernel<<<128, 256>>>((const unsigned*)ei, eiw,
                                    (const unsigned*)bt, btw);
    }
    {
        int mx = (E > N) ? E : N;
        convdeg_kernel<<<(mx + 255) / 256, 256>>>(ei, bt, ew, E, N);
    }
    scan1_kernel<<<nscan, SCAN_TILE>>>(N);
    scan2_kernel<<<1, 512>>>(nscan);
    scan3_kernel<<<nscan, SCAN_TILE>>>(N);
    scatter_kernel<<<(E + 255) / 256, 256>>>(ew, E, N);

    // Horner hops: u2 = S p3 + p2;  u1 = S u2 + p1;  out = S u1 + p0
    {
        int warps_per_block = 8;
        int blocks = (N + warps_per_block - 1) / warps_per_block;
        cudaStreamWaitEvent(s0, g_sp.evG2, 0);
        gather_add_kernel<<<blocks, warps_per_block * 32>>>(y, 4, 3, 5, N);
        cudaStreamWaitEvent(s0, g_sp.evG1, 0);
        gather_add_kernel<<<blocks, warps_per_block * 32>>>(y, 5, 2, 6, N);
        cudaStreamWaitEvent(s0, g_sp.evG0, 0);
        gather_add_kernel<<<blocks, warps_per_block * 32>>>(y, 6, 1, 7, N);
    }

    // GraphNorm + epilogue
    gstats_kernel<<<(N + GR - 1) / GR, 256>>>(N);
    {
        size_t total = (size_t)N * (FDIM / 4);
        final_kernel<<<(int)((total + 255) / 256), 256>>>(
            y, gnms, gnw, gnb, outp, N);
    }
}